// round 1
// baseline (speedup 1.0000x reference)
#include <cuda_runtime.h>
#include <cstdint>

#define Kc   10
#define Hc   224
#define Wc   224
#define BNc  16
#define Tc   15
#define PADc 7
#define SHc  7                 // strip height (224 = 32*7)
#define NSTRIP (Hc/SHc)        // 32
#define AS_W 239               // halo width 238 needed; 239 gives conflict-free stride (239 mod 32 = 15)
#define AS_H (SHc + 2*PADc)    // 21
#define AS_CH (AS_H*AS_W)      // 5019
#define BS_CH (SHc*Wc)         // 1568
#define NSH (Tc*Tc)            // 225
#define EPSF 1e-16f
#define SMEM_BYTES ((Kc*AS_CH + 5*BS_CH)*4)   // 232,120 B < 232,448 limit

__device__ float g_p[NSH*Kc*Kc];   // 22500-entry joint histogram

__global__ void zero_p_kernel() {
    int i = blockIdx.x*blockDim.x + threadIdx.x;
    if (i < NSH*Kc*Kc) g_p[i] = 0.0f;
}

// One block = (y-strip, batch, o-half). 225 active threads; thread t owns shift
// (sy=t/15, sx=t%15) and accumulates 10(n) x 5(o) packed f32x2 pixel-pair sums.
__global__ __launch_bounds__(256, 1)
void hist_kernel(const float* __restrict__ xo, const float* __restrict__ xt) {
    extern __shared__ float sm[];
    float* As = sm;                        // [Kc][AS_H][AS_W] Xo strip + halo (zero-padded)
    float* Bs = sm + Kc*AS_CH;             // [5][SHc][Wc]     Xt strip (this o-half)

    const int strip = blockIdx.x;
    const int c     = blockIdx.y;
    const int oh    = blockIdx.z;
    const int y0    = strip * SHc;
    const int tid   = threadIdx.x;

    // ---- cooperative load: Xo with halo, zero padding outside image ----
    const float* xoc = xo + (size_t)c * Kc * Hc * Wc;
    for (int e = tid; e < Kc*AS_CH; e += 256) {
        int n  = e / AS_CH;
        int r  = (e % AS_CH) / AS_W;
        int ax = e % AS_W;
        int gy = y0 + r - PADc;
        int gx = ax - PADc;
        float v = 0.0f;
        if ((unsigned)gy < (unsigned)Hc && (unsigned)gx < (unsigned)Wc)
            v = xoc[(n*Hc + gy)*Wc + gx];
        As[e] = v;
    }
    // ---- cooperative load: Xt strip (5 channels of this o-half) ----
    const float* xtc = xt + (size_t)c * Kc * Hc * Wc + (size_t)oh * 5 * Hc * Wc;
    for (int e = tid; e < 5*BS_CH; e += 256) {
        int j  = e / BS_CH;
        int rr = e % BS_CH;
        Bs[e] = xtc[j*Hc*Wc + y0*Wc + rr];
    }
    __syncthreads();

    if (tid >= NSH) return;
    const int sy  = tid / Tc;
    const int sxi = tid % Tc;

    unsigned long long acc[50];
    #pragma unroll
    for (int i = 0; i < 50; i++) acc[i] = 0ULL;

    for (int yy = 0; yy < SHc; yy++) {
        const float* a0 = As + (yy + sy)*AS_W + sxi;   // + n*AS_CH per channel
        const float* b0 = Bs + yy*Wc;                  // + j*BS_CH per channel
        #pragma unroll 2
        for (int xx = 0; xx < Wc; xx += 2) {
            unsigned long long av[10];
            #pragma unroll
            for (int n = 0; n < 10; n++) {
                float lo = a0[n*AS_CH + xx];
                float hi = a0[n*AS_CH + xx + 1];
                asm("mov.b64 %0, {%1, %2};" : "=l"(av[n]) : "f"(lo), "f"(hi));
            }
            #pragma unroll
            for (int j = 0; j < 5; j++) {
                float2 b = *reinterpret_cast<const float2*>(b0 + j*BS_CH + xx);
                unsigned long long bv;
                asm("mov.b64 %0, {%1, %2};" : "=l"(bv) : "f"(b.x), "f"(b.y));
                #pragma unroll
                for (int n = 0; n < 10; n++) {
                    asm("fma.rn.f32x2 %0, %1, %2, %0;"
                        : "+l"(acc[j*10 + n]) : "l"(av[n]), "l"(bv));
                }
            }
        }
    }

    // ---- fold pixel-pair halves, accumulate into global histogram ----
    const int s = tid;
    #pragma unroll
    for (int j = 0; j < 5; j++) {
        #pragma unroll
        for (int n = 0; n < 10; n++) {
            float lo, hi;
            asm("mov.b64 {%0, %1}, %2;" : "=f"(lo), "=f"(hi) : "l"(acc[j*10 + n]));
            atomicAdd(&g_p[s*100 + n*10 + (oh*5 + j)], lo + hi);
        }
    }
}

// Single block: min-shift, per-shift normalize + symmetrize, MI-style loss.
__global__ void loss_kernel(float* __restrict__ out) {
    __shared__ float red[256];
    const int t = threadIdx.x;

    float mn = 3.4e38f;
    for (int i = t; i < NSH*100; i += 256) mn = fminf(mn, g_p[i]);
    red[t] = mn; __syncthreads();
    for (int s = 128; s > 0; s >>= 1) {
        if (t < s) red[t] = fminf(red[t], red[t + s]);
        __syncthreads();
    }
    const float pmin = red[0];
    __syncthreads();

    float loss = 0.0f;
    if (t < NSH) {
        const float* q = g_p + t*100;
        float row[10], col[10], S = 0.0f;
        #pragma unroll
        for (int i = 0; i < 10; i++) { row[i] = 0.0f; col[i] = 0.0f; }
        #pragma unroll
        for (int n = 0; n < 10; n++) {
            #pragma unroll
            for (int o = 0; o < 10; o++) {
                float v = q[n*10 + o] - pmin + EPSF;
                S += v; row[n] += v; col[o] += v;
            }
        }
        const float inv2S = 0.5f / S;
        float lp[10];
        #pragma unroll
        for (int i = 0; i < 10; i++)
            lp[i] = logf((row[i] + col[i]) * inv2S + EPSF);   // marginal (symmetric: p_i == p_j)
        #pragma unroll
        for (int n = 0; n < 10; n++) {
            #pragma unroll
            for (int o = 0; o < 10; o++) {
                float v1 = q[n*10 + o] - pmin + EPSF;
                float v2 = q[o*10 + n] - pmin + EPSF;
                float pp = (v1 + v2) * inv2S;
                loss -= pp * (logf(pp + EPSF) - lp[o] - lp[n]);
            }
        }
    }
    red[t] = loss; __syncthreads();
    for (int s = 128; s > 0; s >>= 1) {
        if (t < s) red[t] += red[t + s];
        __syncthreads();
    }
    if (t == 0) out[0] = red[0] / (float)NSH;
}

extern "C" void kernel_launch(void* const* d_in, const int* in_sizes, int n_in,
                              void* d_out, int out_size) {
    const float* xo = (const float*)d_in[0];   // x_out   (16,10,224,224) f32
    const float* xt = (const float*)d_in[1];   // x_tf_out(16,10,224,224) f32
    float* out = (float*)d_out;

    cudaFuncSetAttribute(hist_kernel, cudaFuncAttributeMaxDynamicSharedMemorySize, SMEM_BYTES);

    zero_p_kernel<<<(NSH*Kc*Kc + 255)/256, 256>>>();
    dim3 grid(NSTRIP, BNc, 2);
    hist_kernel<<<grid, 256, SMEM_BYTES>>>(xo, xt);
    loss_kernel<<<1, 256>>>(out);
}